// round 1
// baseline (speedup 1.0000x reference)
#include <cuda_runtime.h>

// Problem constants (fixed by the dataset)
#define BSZ 8
#define QN  500
#define NCL 2
#define TN  400
#define PN  (BSZ*QN)     // 4000 flattened preds
#define NBLOCKS 152      // one persistent block per GB300 SM
#define TPB 416          // 13 warps; threads [0,400) own one target each
#define MAXPPB 32        // >= ceil(PN/NBLOCKS)+1

__global__ __launch_bounds__(TPB, 1)
void matcher_kernel(const float* __restrict__ logits,   // [PN,2]
                    const float* __restrict__ pkp,      // [PN,53]
                    const int*   __restrict__ tids,     // [TN]
                    const float* __restrict__ tkp,      // [TN,53]
                    const int*   __restrict__ nbp,      // scalar num_boxes
                    float*       __restrict__ out)      // [PN,TN]
{
    // per-pred preprocessed data: [0..67] interleaved (Zp[k], Ap[k]) pairs,
    // [68..91] dot vector: Vp[17], Cp[2], (p0-p1), 1.0, s_p, 0, 0
    __shared__ float smP[MAXPPB * 92];

    const int b = blockIdx.x;
    const int pbase = (b * PN) / NBLOCKS;
    const int pend  = ((b + 1) * PN) / NBLOCKS;
    const int npred = pend - pbase;
    const int tid = threadIdx.x;

    // num_boxes: robust scalar read (int32/int64 low word, or float fallback)
    int nbi = *nbp;
    float nb = (nbi > 0 && nbi < (1 << 20)) ? (float)nbi : *(const float*)nbp;
    const float inb = 1.0f / nb;

    // ---- pred preprocessing into shared (one thread per pred, one-time) ----
    if (tid < npred) {
        const int gp = pbase + tid;
        const float l0 = logits[gp * 2 + 0];
        const float l1 = logits[gp * 2 + 1];
        const float m  = fmaxf(l0, l1);
        const float e0 = __expf(l0 - m);
        const float e1 = __expf(l1 - m);
        const float inv = 1.0f / (e0 + e1);
        const float p0 = e0 * inv, p1 = e1 * inv;

        const float* kp = pkp + gp * 53;
        const float c0 = kp[0], c1 = kp[1];
        float* sp = smP + tid * 92;
        #pragma unroll
        for (int k = 0; k < 34; ++k) {
            float z = kp[2 + k];
            sp[2 * k]     = z;                          // Zp[k]
            sp[2 * k + 1] = z + ((k & 1) ? c1 : c0);    // Ap[k]
        }
        float sv = 0.0f;
        #pragma unroll
        for (int j = 0; j < 17; ++j) {
            float v = kp[36 + j];
            sp[68 + j] = v;                             // Vp[j]
            sv = fmaf(v, v, sv);
        }
        sp[85] = c0;
        sp[86] = c1;
        sp[87] = p0 - p1;                               // class delta
        sp[88] = 1.0f;                                  // pairs with s_g
        sp[89] = 0.2f * inb * sv + 0.5f * inb * (c0 * c0 + c1 * c1) - p0;  // s_p + (-p0)
        sp[90] = 0.0f;
        sp[91] = 0.0f;
    }
    __syncthreads();

    // ---- target features into REGISTERS (lane = target, one-time) ----
    const int  t = tid;
    const bool active = (t < TN);
    float zg[34], ag[34], w[17], td[24];
    if (active) {
        const float* tk = tkp + t * 53;
        const float c0 = tk[0], c1 = tk[1];
        #pragma unroll
        for (int k = 0; k < 34; ++k) {
            float z = tk[2 + k];
            zg[k] = z;
            ag[k] = z + ((k & 1) ? c1 : c0);
        }
        float sv = 0.0f;
        #pragma unroll
        for (int j = 0; j < 17; ++j) {
            float v = tk[36 + j];
            w[j]  = 0.5f * inb * v;      // shared weight: offset uses 1x, abs uses 8x
            td[j] = -0.4f * inb * v;     // viz cross term
            sv = fmaf(v, v, sv);
        }
        td[17] = -inb * c0;              // center cross term
        td[18] = -inb * c1;
        td[19] = (float)tids[t];         // class: id * (p0-p1)
        td[20] = 0.2f * inb * sv + 0.5f * inb * (c0 * c0 + c1 * c1);  // s_g
        td[21] = 1.0f;                   // pairs with s_p
        td[22] = 0.0f;
        td[23] = 0.0f;
    } else {
        #pragma unroll
        for (int k = 0; k < 34; ++k) { zg[k] = 0.0f; ag[k] = 0.0f; }
        #pragma unroll
        for (int j = 0; j < 17; ++j) w[j] = 0.0f;
        #pragma unroll
        for (int j = 0; j < 24; ++j) td[j] = 0.0f;
    }

    // ---- main loop: each pred broadcast from shared, targets in registers ----
    for (int p = 0; p < npred; ++p) {
        const float* pp = smP + p * 92;
        float a0 = 0.0f, a1 = 0.0f, a2 = 0.0f, a3 = 0.0f;

        #pragma unroll
        for (int k = 0; k < 34; ++k) {
            float2 za = ((const float2*)pp)[k];          // broadcast LDS.64
            float dz = za.x - zg[k];
            float da = za.y - ag[k];
            float inner = fmaf(fabsf(da), 8.0f, fabsf(dz));
            float wk = w[k >> 1];
            switch (k & 3) {
                case 0:  a0 = fmaf(inner, wk, a0); break;
                case 1:  a1 = fmaf(inner, wk, a1); break;
                case 2:  a2 = fmaf(inner, wk, a2); break;
                default: a3 = fmaf(inner, wk, a3); break;
            }
        }

        #pragma unroll
        for (int j = 0; j < 24; j += 4) {
            float4 pd = *(const float4*)(pp + 68 + j);   // broadcast LDS.128
            a0 = fmaf(pd.x, td[j + 0], a0);
            a1 = fmaf(pd.y, td[j + 1], a1);
            a2 = fmaf(pd.z, td[j + 2], a2);
            a3 = fmaf(pd.w, td[j + 3], a3);
        }

        if (active)
            out[(size_t)(pbase + p) * TN + t] = (a0 + a1) + (a2 + a3);
    }
}

extern "C" void kernel_launch(void* const* d_in, const int* in_sizes, int n_in,
                              void* d_out, int out_size)
{
    const float* logits = (const float*)d_in[0];   // pred_logits   [8,500,2]
    const float* pkp    = (const float*)d_in[1];   // pred_keypoints[8,500,53]
    const int*   tids   = (const int*)  d_in[2];   // tgt_ids       [400]
    const float* tkp    = (const float*)d_in[3];   // tgt_keypoints [400,53]
    const int*   nbp    = (const int*)  d_in[4];   // num_boxes scalar
    (void)in_sizes; (void)n_in; (void)out_size;

    matcher_kernel<<<NBLOCKS, TPB>>>(logits, pkp, tids, tkp, nbp, (float*)d_out);
}